// round 12
// baseline (speedup 1.0000x reference)
#include <cuda_runtime.h>
#include <math.h>

#define BB 64
#define LL 8192
#define DD 64
#define NCHUNK 32
#define CHUNK (LL / NCHUNK)   // 256 rows per chunk

// Scratch (allocation-free rule: __device__ globals)
__device__ float g_pm[BB * NCHUNK];            // partial max
__device__ float g_ps[BB * NCHUNK];            // partial sumexp
__device__ float g_pv[BB * NCHUNK * DD];       // partial weighted v-sum

// ---------------------------------------------------------------------------
// Pass 1 (FUSED): logits + online-softmax weighted v-sum in ONE streaming loop.
// grid = BB*NCHUNK blocks, 256 threads (8 warps).
// Row pair per warp-iteration: lanes 0-15 -> row 2j, lanes 16-31 -> row 2j+1,
// each lane covers d = 4*lane15 .. 4*lane15+3 (LDG.128, fully coalesced).
// Per-warp online softmax: warp-uniform running max m (rescale skipped when
// the max doesn't grow -- warp-uniform branch), per-half running s, per-lane
// float4 vacc. kc and v loads issued back-to-back; unroll 4 => 8 LDG.128
// in flight per warp.
// ---------------------------------------------------------------------------
__global__ __launch_bounds__(256) void collect_fused_kernel(
    const float* __restrict__ q,
    const float* __restrict__ kc,
    const float* __restrict__ v,
    const float* __restrict__ tc_p,
    float* __restrict__ logits_out)
{
    const int b = blockIdx.x / NCHUNK;
    const int c = blockIdx.x % NCHUNK;
    const int l0 = c * CHUNK;
    const int t = threadIdx.x;
    const int warp = t >> 5;
    const int lane = t & 31;
    const int lane15 = lane & 15;
    const int half = lane >> 4;

    __shared__ float slogit[CHUNK];
    __shared__ float wm[8], ws[8];
    __shared__ float4 wv[8][16];

    const float inv_tc = 1.0f / __ldg(tc_p);
    const float4 qv = __ldg((const float4*)(q + b * DD) + lane15);

    const float4* kc4 = (const float4*)(kc + ((size_t)b * LL + l0) * DD);
    const float4* v4b = (const float4*)(v  + ((size_t)b * LL + l0) * DD);

    float m = -1e30f;            // warp-uniform running max
    float s = 0.0f;              // per-half running sumexp (uniform within half)
    float vx = 0.0f, vy = 0.0f, vz = 0.0f, vw = 0.0f;  // per-lane vacc

    #pragma unroll 4
    for (int j = warp; j < CHUNK / 2; j += 8) {
        const int r = 2 * j + half;
        const size_t off = (size_t)r * (DD / 4) + lane15;
        // issue both streaming loads before the reduction chain
        const float4 a  = __ldcs(kc4 + off);
        const float4 vv = __ldcs(v4b + off);

        float p = a.x * qv.x + a.y * qv.y + a.z * qv.z + a.w * qv.w;
        #pragma unroll
        for (int o = 8; o; o >>= 1) p += __shfl_xor_sync(0xffffffffu, p, o);
        const float lg = p * inv_tc;                  // uniform within half
        if (lane15 == 0) slogit[r] = lg;

        const float lg_other = __shfl_xor_sync(0xffffffffu, lg, 16);
        const float mn = fmaxf(m, fmaxf(lg, lg_other));   // warp-uniform
        if (mn > m) {                                     // warp-uniform branch
            const float cs = __expf(m - mn);              // rescale factor
            s  *= cs;
            vx *= cs; vy *= cs; vz *= cs; vw *= cs;
            m = mn;
        }
        const float e = __expf(lg - m);                   // this half's weight
        s  += e;
        vx += e * vv.x;
        vy += e * vv.y;
        vz += e * vv.z;
        vw += e * vv.w;
    }

    // combine the two halves of the warp
    const float s_tot = s + __shfl_xor_sync(0xffffffffu, s, 16);
    vx += __shfl_xor_sync(0xffffffffu, vx, 16);
    vy += __shfl_xor_sync(0xffffffffu, vy, 16);
    vz += __shfl_xor_sync(0xffffffffu, vz, 16);
    vw += __shfl_xor_sync(0xffffffffu, vw, 16);

    if (lane == 0) { wm[warp] = m; ws[warp] = s_tot; }
    if (lane < 16) wv[warp][lane15] = make_float4(vx, vy, vz, vw);
    __syncthreads();

    // coalesced logits write (CHUNK == blockDim)
    __stcs(logits_out + (size_t)b * LL + l0 + t, slogit[t]);

    // merge 8 warp partials -> chunk partial
    if (t < DD) {
        float M = wm[0];
        #pragma unroll
        for (int i = 1; i < 8; i++) M = fmaxf(M, wm[i]);
        float Z = 0.0f, acc = 0.0f;
        #pragma unroll
        for (int i = 0; i < 8; i++) {
            const float sc = __expf(wm[i] - M);
            Z   += ws[i] * sc;
            acc += ((const float*)&wv[i][0])[t] * sc;
        }
        g_pv[((size_t)b * NCHUNK + c) * DD + t] = acc;
        if (t == 0) { g_pm[b * NCHUNK + c] = M; g_ps[b * NCHUNK + c] = Z; }
    }
}

// ---------------------------------------------------------------------------
// Pass 2 (diffuse + inlined combine): gate * attn, streamed.
// 256 threads = 8 warps; each warp handles 8 rows (2 rows per LDG.128).
// grid = BB * LL / 64 blocks. Threads t<64 recompute attn[b] from the chunk
// partials (L2-resident) while the kd loads are in flight.
// ---------------------------------------------------------------------------
#define ROWS_PER_WARP 8
#define ROWS_PER_BLOCK (8 * ROWS_PER_WARP)   // 64
#define BLOCKS_PER_BATCH (LL / ROWS_PER_BLOCK)

__global__ __launch_bounds__(256) void diffuse_kernel(
    const float* __restrict__ q,
    const float* __restrict__ kd,
    const float* __restrict__ td_p,
    float* __restrict__ out)
{
    const int b = blockIdx.x / BLOCKS_PER_BATCH;
    const int rb = blockIdx.x % BLOCKS_PER_BATCH;
    const int t = threadIdx.x;
    const int warp = t >> 5;
    const int lane = t & 31;
    const int lane15 = lane & 15;
    const int half = lane >> 4;

    __shared__ float sa[DD];

    const float inv_td = 1.0f / __ldg(td_p);
    const float4 qv = __ldg((const float4*)(q + b * DD) + lane15);

    const int l_base = rb * ROWS_PER_BLOCK + warp * ROWS_PER_WARP;
    const size_t row0 = ((size_t)b * LL + l_base) * DD;
    const float4* kd4 = (const float4*)(kd + row0);

    // 4 LDG.128 per warp cover 8 rows (lanes 0-15 even row, 16-31 odd row)
    float4 a0 = __ldcs(kd4 + (size_t)(0 + half) * (DD / 4) + lane15);
    float4 a1 = __ldcs(kd4 + (size_t)(2 + half) * (DD / 4) + lane15);
    float4 a2 = __ldcs(kd4 + (size_t)(4 + half) * (DD / 4) + lane15);
    float4 a3 = __ldcs(kd4 + (size_t)(6 + half) * (DD / 4) + lane15);

    // inlined combine: attn[b][t] from chunk partials (overlaps load latency)
    if (t < DD) {
        float M = g_pm[b * NCHUNK];
        #pragma unroll 8
        for (int c = 1; c < NCHUNK; c++)
            M = fmaxf(M, g_pm[b * NCHUNK + c]);
        float Z = 0.0f, acc = 0.0f;
        #pragma unroll 8
        for (int c = 0; c < NCHUNK; c++) {
            const float sc = __expf(g_pm[b * NCHUNK + c] - M);
            Z   += g_ps[b * NCHUNK + c] * sc;
            acc += g_pv[((size_t)b * NCHUNK + c) * DD + t] * sc;
        }
        sa[t] = acc / Z;
    }

    float p0 = a0.x * qv.x + a0.y * qv.y + a0.z * qv.z + a0.w * qv.w;
    float p1 = a1.x * qv.x + a1.y * qv.y + a1.z * qv.z + a1.w * qv.w;
    float p2 = a2.x * qv.x + a2.y * qv.y + a2.z * qv.z + a2.w * qv.w;
    float p3 = a3.x * qv.x + a3.y * qv.y + a3.z * qv.z + a3.w * qv.w;
    #pragma unroll
    for (int o = 8; o; o >>= 1) {
        p0 += __shfl_xor_sync(0xffffffffu, p0, o);
        p1 += __shfl_xor_sync(0xffffffffu, p1, o);
        p2 += __shfl_xor_sync(0xffffffffu, p2, o);
        p3 += __shfl_xor_sync(0xffffffffu, p3, o);
    }
    const float g0 = 1.0f / (1.0f + __expf(-p0 * inv_td));
    const float g1 = 1.0f / (1.0f + __expf(-p1 * inv_td));
    const float g2 = 1.0f / (1.0f + __expf(-p2 * inv_td));
    const float g3 = 1.0f / (1.0f + __expf(-p3 * inv_td));

    __syncthreads();
    const float4 av = ((const float4*)sa)[lane15];

    float4* out4 = (float4*)(out + row0);
    __stcs(out4 + (size_t)(0 + half) * (DD / 4) + lane15,
           make_float4(g0 * av.x, g0 * av.y, g0 * av.z, g0 * av.w));
    __stcs(out4 + (size_t)(2 + half) * (DD / 4) + lane15,
           make_float4(g1 * av.x, g1 * av.y, g1 * av.z, g1 * av.w));
    __stcs(out4 + (size_t)(4 + half) * (DD / 4) + lane15,
           make_float4(g2 * av.x, g2 * av.y, g2 * av.z, g2 * av.w));
    __stcs(out4 + (size_t)(6 + half) * (DD / 4) + lane15,
           make_float4(g3 * av.x, g3 * av.y, g3 * av.z, g3 * av.w));
}

// ---------------------------------------------------------------------------
extern "C" void kernel_launch(void* const* d_in, const int* in_sizes, int n_in,
                              void* d_out, int out_size)
{
    const float* q  = (const float*)d_in[0];
    const float* kc = (const float*)d_in[1];
    const float* kd = (const float*)d_in[2];
    const float* v  = (const float*)d_in[3];
    const float* tc = (const float*)d_in[4];
    const float* td = (const float*)d_in[5];

    float* out    = (float*)d_out;                        // [B, L, D]
    float* logits = (float*)d_out + (size_t)BB * LL * DD; // [B, L]

    collect_fused_kernel<<<BB * NCHUNK, 256>>>(q, kc, v, tc, logits);
    diffuse_kernel<<<BB * BLOCKS_PER_BATCH, 256>>>(q, kd, td, out);
}